// round 6
// baseline (speedup 1.0000x reference)
#include <cuda_runtime.h>
#include <cstdint>

typedef unsigned long long ull;

#define BN_TOTAL 16384   // B*N
#define NN 2048
#define XSTRIDE 20       // floats per smem row (80B: keeps 16B cp.async alignment)
#define TILEF (64 * XSTRIDE)   // 1280 floats = 5120 B per tile

__device__ __align__(16) float g_eip[BN_TOTAL];
__device__ __align__(16) float g_ein[BN_TOTAL];
__device__ __align__(16) float g_ejp[BN_TOTAL];
__device__ __align__(16) float g_ejn[BN_TOTAL];

__device__ __forceinline__ void fma2(ull& acc, ull x, ull w) {
    asm("fma.rn.f32x2 %0, %1, %2, %0;" : "+l"(acc) : "l"(x), "l"(w));
}
__device__ __forceinline__ ull pack2(float v) {
    ull r; unsigned u = __float_as_uint(v);
    asm("mov.b64 %0, {%1, %1};" : "=l"(r) : "r"(u));
    return r;
}
__device__ __forceinline__ void cp16(uint32_t dst, const void* src) {
    asm volatile("cp.async.cg.shared.global [%0], [%1], 16;" :: "r"(dst), "l"(src));
}

// ---------------------------------------------------------------------------
// k1: fused TimeBlock + dot -> exp factors. 4 warps/CTA, each warp processes
// 4 consecutive bn tiles with a 2-deep cp.async double buffer, so X streaming
// overlaps the FFMA phase. relu(c1+b1+sig(c2+b2)+c3+b3)=relu(conv(w1+w3)+..)
// ---------------------------------------------------------------------------
__global__ void __launch_bounds__(128) score_kernel(
    const float* __restrict__ X,
    const float* __restrict__ cw1, const float* __restrict__ cw2,
    const float* __restrict__ cw3,
    const float* __restrict__ cb1, const float* __restrict__ cb2,
    const float* __restrict__ cb3,
    const float* __restrict__ fcw, const float* __restrict__ fcbp)
{
    __shared__ __align__(16) float sX[4 * 2 * TILEF];   // 40 KB
    __shared__ __align__(16) float sW[384];             // [2][k*16+ci][co]
    __shared__ float sFC[496];

    int tid = threadIdx.x;
    for (int i = tid; i < 384; i += 128) {
        int c   = i / 192;
        int r   = i % 192;
        int pos = r >> 2, co = r & 3;
        int k   = pos >> 4, ci = pos & 15;
        int src = co * 48 + ci * 3 + k;
        sW[i] = (c == 0) ? (cw1[src] + cw3[src]) : cw2[src];
    }
    for (int i = tid; i < 496; i += 128) sFC[i] = fcw[i];
    __syncthreads();   // weights ready; warps fully independent after this

    int warp = tid >> 5, lane = tid & 31;
    int bn0 = blockIdx.x * 16 + warp * 4;

    float* buf[2] = { sX + warp * 2 * TILEF, sX + warp * 2 * TILEF + TILEF };
    uint32_t bufs[2] = { (uint32_t)__cvta_generic_to_shared(buf[0]),
                         (uint32_t)__cvta_generic_to_shared(buf[1]) };

    float bS[4], b2_[4];
    #pragma unroll
    for (int co = 0; co < 4; co++) { bS[co] = cb1[co] + cb3[co]; b2_[co] = cb2[co]; }
    float fcb = fcbp[0];

    // prologue: load tile 0
    {
        const float* Xg = X + (size_t)bn0 * 1024;
        #pragma unroll
        for (int q = 0; q < 8; q++) {
            int f = q * 32 + lane;
            int row = f >> 2, c4 = (f & 3) * 4;
            cp16(bufs[0] + (row * XSTRIDE + c4) * 4, Xg + f * 4);
        }
        asm volatile("cp.async.commit_group;");
    }

    #pragma unroll 1
    for (int it = 0; it < 4; it++) {
        if (it < 3) {   // prefetch next tile into other buffer
            const float* Xg = X + (size_t)(bn0 + it + 1) * 1024;
            uint32_t d = bufs[(it + 1) & 1];
            #pragma unroll
            for (int q = 0; q < 8; q++) {
                int f = q * 32 + lane;
                int row = f >> 2, c4 = (f & 3) * 4;
                cp16(d + (row * XSTRIDE + c4) * 4, Xg + f * 4);
            }
            asm volatile("cp.async.commit_group;");
            asm volatile("cp.async.wait_group 1;");
        } else {
            asm volatile("cp.async.wait_group 0;");
        }
        __syncwarp();

        const float* wb = buf[it & 1];
        int to  = lane;
        int to2 = lane + 32;

        ull A0 = 0, A1 = 0, A2 = 0, A3 = 0;
        ull B0 = 0, B1 = 0, B2 = 0, B3 = 0;

        #pragma unroll
        for (int k = 0; k < 3; k++) {
            const float4* xk1 = (const float4*)(wb + (to + k) * XSTRIDE);
            const float4* xk2 = (const float4*)(wb + (to + 32 + k) * XSTRIDE);
            // NOTE: row (to+k) cols 0..15 -- but conv needs x[to+k][ci]; row data
            // at wb[(to+k)*XSTRIDE + ci], and k-th tap uses row to+k. Correct.
            float4 xa4[4], xb4[4];
            #pragma unroll
            for (int c4 = 0; c4 < 4; c4++) { xa4[c4] = xk1[c4]; xb4[c4] = xk2[c4]; }
            const float* xa = (const float*)xa4;
            const float* xb = (const float*)xb4;
            #pragma unroll
            for (int ci = 0; ci < 16; ci++) {
                int wbase = (k * 16 + ci) * 4;
                ull w0 = *(const ull*)(sW + wbase);
                ull w1 = *(const ull*)(sW + wbase + 2);
                ull w2 = *(const ull*)(sW + 192 + wbase);
                ull w3 = *(const ull*)(sW + 192 + wbase + 2);
                ull qa = pack2(xa[ci]);
                ull qb = pack2(xb[ci]);
                fma2(A0, qa, w0); fma2(A1, qa, w1);
                fma2(A2, qa, w2); fma2(A3, qa, w3);
                fma2(B0, qb, w0); fma2(B1, qb, w1);
                fma2(B2, qb, w2); fma2(B3, qb, w3);
            }
        }

        float si = 0.f, sj = 0.f;
        {
            float yS[4], y2[4];
            yS[0] = __uint_as_float((unsigned)A0); yS[1] = __uint_as_float((unsigned)(A0 >> 32));
            yS[2] = __uint_as_float((unsigned)A1); yS[3] = __uint_as_float((unsigned)(A1 >> 32));
            y2[0] = __uint_as_float((unsigned)A2); y2[1] = __uint_as_float((unsigned)(A2 >> 32));
            y2[2] = __uint_as_float((unsigned)A3); y2[3] = __uint_as_float((unsigned)(A3 >> 32));
            #pragma unroll
            for (int co = 0; co < 4; co++) {
                float sg = 1.0f / (1.0f + __expf(-(y2[co] + b2_[co])));
                float tv = fmaxf(yS[co] + bS[co] + sg, 0.0f);
                si = fmaf(tv, sFC[to * 4 + co], si);
                sj = fmaf(tv, sFC[248 + to * 4 + co], sj);
            }
        }
        if (to2 < 62) {
            float yS[4], y2[4];
            yS[0] = __uint_as_float((unsigned)B0); yS[1] = __uint_as_float((unsigned)(B0 >> 32));
            yS[2] = __uint_as_float((unsigned)B1); yS[3] = __uint_as_float((unsigned)(B1 >> 32));
            y2[0] = __uint_as_float((unsigned)B2); y2[1] = __uint_as_float((unsigned)(B2 >> 32));
            y2[2] = __uint_as_float((unsigned)B3); y2[3] = __uint_as_float((unsigned)(B3 >> 32));
            #pragma unroll
            for (int co = 0; co < 4; co++) {
                float sg = 1.0f / (1.0f + __expf(-(y2[co] + b2_[co])));
                float tv = fmaxf(yS[co] + bS[co] + sg, 0.0f);
                si = fmaf(tv, sFC[to2 * 4 + co], si);
                sj = fmaf(tv, sFC[248 + to2 * 4 + co], sj);
            }
        }
        #pragma unroll
        for (int off = 16; off > 0; off >>= 1) {
            si += __shfl_xor_sync(0xffffffffu, si, off);
            sj += __shfl_xor_sync(0xffffffffu, sj, off);
        }
        if (lane == 0) {
            int bn = bn0 + it;
            float sif = si + fcb;
            g_eip[bn] = __expf(sif);
            g_ein[bn] = __expf(0.01f * sif);
            g_ejp[bn] = __expf(sj);
            g_ejn[bn] = __expf(0.01f * sj);
        }
    }
}

// ---------------------------------------------------------------------------
// k2: masked softmax, pure-FMA form (A values in {0,1} used as numbers):
//   denom = 2048 + sum_j a_j*(e_j - 1)     [one FFMA per element]
//   out_j = e_j * a_j * r                   [plain MULs]
// One block = 4 rows of one batch; P/Q column regs shared by the 4 rows;
// A reloaded (L1-hot) in the write phase.
// ---------------------------------------------------------------------------
__global__ void __launch_bounds__(256) softmax_kernel(
    const float* __restrict__ A, float* __restrict__ out)
{
    int tile = blockIdx.x;          // 4096 = 8 batches x 512 row-tiles
    int it   = tile & 511;
    int b    = tile >> 9;
    int i0   = it * 4;
    int t    = threadIdx.x;
    int j0   = t * 4;

    float4 P0 = *(const float4*)(g_ejp + b * NN + j0);
    float4 P1 = *(const float4*)(g_ejp + b * NN + j0 + 1024);
    float4 Q0 = *(const float4*)(g_ejn + b * NN + j0);
    float4 Q1 = *(const float4*)(g_ejn + b * NN + j0 + 1024);

    float Eip[4], Ein[4], acc[4];

    #pragma unroll
    for (int ii = 0; ii < 4; ii++) {
        int i = i0 + ii;
        float4 a0 = __ldg((const float4*)(A + (size_t)i * NN + j0));
        float4 a1 = __ldg((const float4*)(A + (size_t)i * NN + j0 + 1024));
        float Ep = __ldg(g_eip + b * NN + i);
        float En = __ldg(g_ein + b * NN + i);
        Eip[ii] = Ep; Ein[ii] = En;
        float s = 0.f;
        s = fmaf(fmaxf(Ep * P0.x, En * Q0.x) - 1.f, a0.x, s);
        s = fmaf(fmaxf(Ep * P0.y, En * Q0.y) - 1.f, a0.y, s);
        s = fmaf(fmaxf(Ep * P0.z, En * Q0.z) - 1.f, a0.z, s);
        s = fmaf(fmaxf(Ep * P0.w, En * Q0.w) - 1.f, a0.w, s);
        s = fmaf(fmaxf(Ep * P1.x, En * Q1.x) - 1.f, a1.x, s);
        s = fmaf(fmaxf(Ep * P1.y, En * Q1.y) - 1.f, a1.y, s);
        s = fmaf(fmaxf(Ep * P1.z, En * Q1.z) - 1.f, a1.z, s);
        s = fmaf(fmaxf(Ep * P1.w, En * Q1.w) - 1.f, a1.w, s);
        acc[ii] = s;
    }

    #pragma unroll
    for (int off = 16; off > 0; off >>= 1) {
        acc[0] += __shfl_xor_sync(0xffffffffu, acc[0], off);
        acc[1] += __shfl_xor_sync(0xffffffffu, acc[1], off);
        acc[2] += __shfl_xor_sync(0xffffffffu, acc[2], off);
        acc[3] += __shfl_xor_sync(0xffffffffu, acc[3], off);
    }

    __shared__ float red[4][8];
    __shared__ float s_r[4];
    if ((t & 31) == 0) {
        int w = t >> 5;
        red[0][w] = acc[0]; red[1][w] = acc[1];
        red[2][w] = acc[2]; red[3][w] = acc[3];
    }
    __syncthreads();
    if (t < 4) {
        float s = 2048.f + red[t][0] + red[t][1] + red[t][2] + red[t][3]
                         + red[t][4] + red[t][5] + red[t][6] + red[t][7];
        s_r[t] = 1.0f / s;
    }
    __syncthreads();

    #pragma unroll
    for (int ii = 0; ii < 4; ii++) {
        int i = i0 + ii;
        float r = s_r[ii];
        float Ep = Eip[ii], En = Ein[ii];
        float4 a0 = __ldg((const float4*)(A + (size_t)i * NN + j0));
        float4 a1 = __ldg((const float4*)(A + (size_t)i * NN + j0 + 1024));
        float* O = out + ((size_t)(b * NN + i)) * NN;
        float4 o0, o1;
        o0.x = fmaxf(Ep * P0.x, En * Q0.x) * a0.x * r;
        o0.y = fmaxf(Ep * P0.y, En * Q0.y) * a0.y * r;
        o0.z = fmaxf(Ep * P0.z, En * Q0.z) * a0.z * r;
        o0.w = fmaxf(Ep * P0.w, En * Q0.w) * a0.w * r;
        o1.x = fmaxf(Ep * P1.x, En * Q1.x) * a1.x * r;
        o1.y = fmaxf(Ep * P1.y, En * Q1.y) * a1.y * r;
        o1.z = fmaxf(Ep * P1.z, En * Q1.z) * a1.z * r;
        o1.w = fmaxf(Ep * P1.w, En * Q1.w) * a1.w * r;
        __stcs((float4*)(O + j0), o0);
        __stcs((float4*)(O + j0 + 1024), o1);
    }
}

// ---------------------------------------------------------------------------
extern "C" void kernel_launch(void* const* d_in, const int* in_sizes, int n_in,
                              void* d_out, int out_size) {
    const float* X   = (const float*)d_in[0];
    const float* A   = (const float*)d_in[1];
    const float* cw1 = (const float*)d_in[2];
    const float* cb1 = (const float*)d_in[3];
    const float* cw2 = (const float*)d_in[4];
    const float* cb2 = (const float*)d_in[5];
    const float* cw3 = (const float*)d_in[6];
    const float* cb3 = (const float*)d_in[7];
    const float* fcw = (const float*)d_in[8];
    const float* fcb = (const float*)d_in[9];
    float* out = (float*)d_out;

    score_kernel<<<BN_TOTAL / 16, 128>>>(X, cw1, cw2, cw3, cb1, cb2, cb3, fcw, fcb);
    softmax_kernel<<<4096, 256>>>(A, out);
}

// round 7
// speedup vs baseline: 1.0758x; 1.0758x over previous
#include <cuda_runtime.h>
#include <cstdint>

typedef unsigned long long ull;

#define BN_TOTAL 16384   // B*N
#define NN 2048
#define XSTRIDE 20       // floats per smem row; start banks are multiples of 4
                         // -> LDS.128 wavefronts conflict-free

__device__ __align__(16) float g_eip[BN_TOTAL];
__device__ __align__(16) float g_ein[BN_TOTAL];
__device__ __align__(16) float g_ejp[BN_TOTAL];
__device__ __align__(16) float g_ejn[BN_TOTAL];

__device__ __forceinline__ void fma2(ull& acc, ull x, ull w) {
    asm("fma.rn.f32x2 %0, %1, %2, %0;" : "+l"(acc) : "l"(x), "l"(w));
}
__device__ __forceinline__ ull pack2(float v) {
    ull r; unsigned u = __float_as_uint(v);
    asm("mov.b64 %0, {%1, %1};" : "=l"(r) : "r"(u));
    return r;
}
__device__ __forceinline__ void cp16(uint32_t dst, const void* src) {
    asm volatile("cp.async.cg.shared.global [%0], [%1], 16;" :: "r"(dst), "l"(src));
}

// ---------------------------------------------------------------------------
// k1: fused TimeBlock + dot -> exp factors per (b,n).
// relu(c1+b1+sig(c2+b2)+c3+b3) = relu(conv(w1+w3)+(b1+b3)+sig(conv(w2)+b2)).
// 8 warps/CTA, one bn tile per warp, warps fully decoupled after weight load
// (cp.async + __syncwarp only). Weight pairs and x rows read via LDS.128.
// Lane covers to=lane and to2=lane+32.
// ---------------------------------------------------------------------------
__global__ void __launch_bounds__(256) score_kernel(
    const float* __restrict__ X,
    const float* __restrict__ cw1, const float* __restrict__ cw2,
    const float* __restrict__ cw3,
    const float* __restrict__ cb1, const float* __restrict__ cb2,
    const float* __restrict__ cb3,
    const float* __restrict__ fcw, const float* __restrict__ fcbp)
{
    __shared__ __align__(16) float sX[8 * 64 * XSTRIDE];  // 40 KB
    __shared__ __align__(16) float sW[384];               // [2][k*16+ci][co]
    __shared__ float sFC[496];

    int tid = threadIdx.x;
    for (int i = tid; i < 384; i += 256) {
        int c   = i / 192;
        int r   = i % 192;
        int pos = r >> 2, co = r & 3;
        int k   = pos >> 4, ci = pos & 15;
        int src = co * 48 + ci * 3 + k;
        sW[i] = (c == 0) ? (cw1[src] + cw3[src]) : cw2[src];
    }
    for (int i = tid; i < 496; i += 256) sFC[i] = fcw[i];
    __syncthreads();   // weights ready; warps independent from here

    int warp = tid >> 5, lane = tid & 31;
    int bn = blockIdx.x * 8 + warp;

    float* wbuf = sX + warp * (64 * XSTRIDE);
    uint32_t wbuf_s = (uint32_t)__cvta_generic_to_shared(wbuf);
    const float* Xg = X + (size_t)bn * 1024;

    #pragma unroll
    for (int q = 0; q < 8; q++) {
        int f = q * 32 + lane;
        int row = f >> 2, c4 = (f & 3) * 4;
        cp16(wbuf_s + (row * XSTRIDE + c4) * 4, Xg + f * 4);
    }
    asm volatile("cp.async.commit_group;");
    asm volatile("cp.async.wait_group 0;");
    __syncwarp();

    int to  = lane;
    int to2 = lane + 32;

    ull A0 = 0, A1 = 0, A2 = 0, A3 = 0;
    ull B0 = 0, B1 = 0, B2 = 0, B3 = 0;
    const float* x1 = wbuf + to * XSTRIDE;
    const float* x2 = x1 + 32 * XSTRIDE;

    #pragma unroll
    for (int k = 0; k < 3; k++) {
        // 16 x-values for tap k, rows to+k / to2+k, via 4 LDS.128 each
        float4 xa4[4], xb4[4];
        const float4* pa = (const float4*)(x1 + k * XSTRIDE);
        const float4* pb = (const float4*)(x2 + k * XSTRIDE);
        #pragma unroll
        for (int c4 = 0; c4 < 4; c4++) { xa4[c4] = pa[c4]; xb4[c4] = pb[c4]; }
        const float* xa = (const float*)xa4;
        const float* xb = (const float*)xb4;
        #pragma unroll
        for (int ci = 0; ci < 16; ci++) {
            int widx = (k * 16 + ci) * 4;
            ulonglong2 wS = *(const ulonglong2*)(sW + widx);        // w0,w1
            ulonglong2 w2v = *(const ulonglong2*)(sW + 192 + widx); // w2,w3
            ull qa = pack2(xa[ci]);
            ull qb = pack2(xb[ci]);
            fma2(A0, qa, wS.x);  fma2(A1, qa, wS.y);
            fma2(A2, qa, w2v.x); fma2(A3, qa, w2v.y);
            fma2(B0, qb, wS.x);  fma2(B1, qb, wS.y);
            fma2(B2, qb, w2v.x); fma2(B3, qb, w2v.y);
        }
    }

    float bS[4], b2_[4];
    #pragma unroll
    for (int co = 0; co < 4; co++) { bS[co] = cb1[co] + cb3[co]; b2_[co] = cb2[co]; }

    float si = 0.f, sj = 0.f;
    {
        float yS[4], y2[4];
        yS[0] = __uint_as_float((unsigned)A0); yS[1] = __uint_as_float((unsigned)(A0 >> 32));
        yS[2] = __uint_as_float((unsigned)A1); yS[3] = __uint_as_float((unsigned)(A1 >> 32));
        y2[0] = __uint_as_float((unsigned)A2); y2[1] = __uint_as_float((unsigned)(A2 >> 32));
        y2[2] = __uint_as_float((unsigned)A3); y2[3] = __uint_as_float((unsigned)(A3 >> 32));
        #pragma unroll
        for (int co = 0; co < 4; co++) {
            float sg = 1.0f / (1.0f + __expf(-(y2[co] + b2_[co])));
            float tv = fmaxf(yS[co] + bS[co] + sg, 0.0f);
            si = fmaf(tv, sFC[to * 4 + co], si);
            sj = fmaf(tv, sFC[248 + to * 4 + co], sj);
        }
    }
    if (to2 < 62) {
        float yS[4], y2[4];
        yS[0] = __uint_as_float((unsigned)B0); yS[1] = __uint_as_float((unsigned)(B0 >> 32));
        yS[2] = __uint_as_float((unsigned)B1); yS[3] = __uint_as_float((unsigned)(B1 >> 32));
        y2[0] = __uint_as_float((unsigned)B2); y2[1] = __uint_as_float((unsigned)(B2 >> 32));
        y2[2] = __uint_as_float((unsigned)B3); y2[3] = __uint_as_float((unsigned)(B3 >> 32));
        #pragma unroll
        for (int co = 0; co < 4; co++) {
            float sg = 1.0f / (1.0f + __expf(-(y2[co] + b2_[co])));
            float tv = fmaxf(yS[co] + bS[co] + sg, 0.0f);
            si = fmaf(tv, sFC[to2 * 4 + co], si);
            sj = fmaf(tv, sFC[248 + to2 * 4 + co], sj);
        }
    }
    #pragma unroll
    for (int off = 16; off > 0; off >>= 1) {
        si += __shfl_xor_sync(0xffffffffu, si, off);
        sj += __shfl_xor_sync(0xffffffffu, sj, off);
    }
    if (lane == 0) {
        float fcb = fcbp[0];
        float sif = si + fcb;
        g_eip[bn] = __expf(sif);
        g_ein[bn] = __expf(0.01f * sif);
        g_ejp[bn] = __expf(sj);
        g_ejn[bn] = __expf(0.01f * sj);
    }
}

// ---------------------------------------------------------------------------
// k2: masked softmax, pure-FMA form (A in {0,1} used as numbers):
//   denom = 2048 + sum_j a_j*(e_j - 1);  out_j = e_j * a_j / denom.
// One block = 4 rows of one batch; P/Q column regs shared by the 4 rows.
// launch_bounds(256,4) caps regs at 64 -> 4 CTAs/SM (50% occ). Eip/Ein and
// A reloaded in the write phase (L1-hot).
// ---------------------------------------------------------------------------
__global__ void __launch_bounds__(256, 4) softmax_kernel(
    const float* __restrict__ A, float* __restrict__ out)
{
    int tile = blockIdx.x;          // 4096 = 8 batches x 512 row-tiles
    int it   = tile & 511;
    int b    = tile >> 9;
    int i0   = it * 4;
    int t    = threadIdx.x;
    int j0   = t * 4;

    float4 P0 = *(const float4*)(g_ejp + b * NN + j0);
    float4 P1 = *(const float4*)(g_ejp + b * NN + j0 + 1024);
    float4 Q0 = *(const float4*)(g_ejn + b * NN + j0);
    float4 Q1 = *(const float4*)(g_ejn + b * NN + j0 + 1024);

    float acc[4];

    #pragma unroll
    for (int ii = 0; ii < 4; ii++) {
        int i = i0 + ii;
        float4 a0 = __ldg((const float4*)(A + (size_t)i * NN + j0));
        float4 a1 = __ldg((const float4*)(A + (size_t)i * NN + j0 + 1024));
        float Ep = __ldg(g_eip + b * NN + i);
        float En = __ldg(g_ein + b * NN + i);
        float s = 0.f;
        s = fmaf(fmaxf(Ep * P0.x, En * Q0.x) - 1.f, a0.x, s);
        s = fmaf(fmaxf(Ep * P0.y, En * Q0.y) - 1.f, a0.y, s);
        s = fmaf(fmaxf(Ep * P0.z, En * Q0.z) - 1.f, a0.z, s);
        s = fmaf(fmaxf(Ep * P0.w, En * Q0.w) - 1.f, a0.w, s);
        s = fmaf(fmaxf(Ep * P1.x, En * Q1.x) - 1.f, a1.x, s);
        s = fmaf(fmaxf(Ep * P1.y, En * Q1.y) - 1.f, a1.y, s);
        s = fmaf(fmaxf(Ep * P1.z, En * Q1.z) - 1.f, a1.z, s);
        s = fmaf(fmaxf(Ep * P1.w, En * Q1.w) - 1.f, a1.w, s);
        acc[ii] = s;
    }

    #pragma unroll
    for (int off = 16; off > 0; off >>= 1) {
        acc[0] += __shfl_xor_sync(0xffffffffu, acc[0], off);
        acc[1] += __shfl_xor_sync(0xffffffffu, acc[1], off);
        acc[2] += __shfl_xor_sync(0xffffffffu, acc[2], off);
        acc[3] += __shfl_xor_sync(0xffffffffu, acc[3], off);
    }

    __shared__ float red[4][8];
    __shared__ float s_r[4];
    if ((t & 31) == 0) {
        int w = t >> 5;
        red[0][w] = acc[0]; red[1][w] = acc[1];
        red[2][w] = acc[2]; red[3][w] = acc[3];
    }
    __syncthreads();
    if (t < 4) {
        float s = 2048.f + red[t][0] + red[t][1] + red[t][2] + red[t][3]
                         + red[t][4] + red[t][5] + red[t][6] + red[t][7];
        s_r[t] = 1.0f / s;
    }
    __syncthreads();

    #pragma unroll
    for (int ii = 0; ii < 4; ii++) {
        int i = i0 + ii;
        float r = s_r[ii];
        float Ep = __ldg(g_eip + b * NN + i);   // L1 hit
        float En = __ldg(g_ein + b * NN + i);
        float4 a0 = __ldg((const float4*)(A + (size_t)i * NN + j0));
        float4 a1 = __ldg((const float4*)(A + (size_t)i * NN + j0 + 1024));
        float* O = out + ((size_t)(b * NN + i)) * NN;
        float4 o0, o1;
        o0.x = fmaxf(Ep * P0.x, En * Q0.x) * a0.x * r;
        o0.y = fmaxf(Ep * P0.y, En * Q0.y) * a0.y * r;
        o0.z = fmaxf(Ep * P0.z, En * Q0.z) * a0.z * r;
        o0.w = fmaxf(Ep * P0.w, En * Q0.w) * a0.w * r;
        o1.x = fmaxf(Ep * P1.x, En * Q1.x) * a1.x * r;
        o1.y = fmaxf(Ep * P1.y, En * Q1.y) * a1.y * r;
        o1.z = fmaxf(Ep * P1.z, En * Q1.z) * a1.z * r;
        o1.w = fmaxf(Ep * P1.w, En * Q1.w) * a1.w * r;
        __stcs((float4*)(O + j0), o0);
        __stcs((float4*)(O + j0 + 1024), o1);
    }
}

// ---------------------------------------------------------------------------
extern "C" void kernel_launch(void* const* d_in, const int* in_sizes, int n_in,
                              void* d_out, int out_size) {
    const float* X   = (const float*)d_in[0];
    const float* A   = (const float*)d_in[1];
    const float* cw1 = (const float*)d_in[2];
    const float* cb1 = (const float*)d_in[3];
    const float* cw2 = (const float*)d_in[4];
    const float* cb2 = (const float*)d_in[5];
    const float* cw3 = (const float*)d_in[6];
    const float* cb3 = (const float*)d_in[7];
    const float* fcw = (const float*)d_in[8];
    const float* fcb = (const float*)d_in[9];
    float* out = (float*)d_out;

    score_kernel<<<BN_TOTAL / 8, 256>>>(X, cw1, cw2, cw3, cb1, cb2, cb3, fcw, fcb);
    softmax_kernel<<<4096, 256>>>(A, out);
}